// round 2
// baseline (speedup 1.0000x reference)
#include <cuda_runtime.h>
#include <cuda_bf16.h>
#include <cstdint>

#define XP 136   // bf16 pitch for x tiles [d][n]
#define AP 136   // bf16 pitch for A tiles [k][n]
#define CP 136   // bf16 pitch for codeword tiles [k][d]
#define SP 132   // fp32 pitch for sl/A [k][n]

struct Sm {
    __nv_bfloat16 xhi[128 * XP];
    __nv_bfloat16 xlo[128 * XP];
    __nv_bfloat16 chi[32 * CP];
    __nv_bfloat16 clo[32 * CP];
    __nv_bfloat16 ahi[32 * AP];
    __nv_bfloat16 alo[32 * AP];
    float slA[32 * SP];
    float x2[128];
    float x2p[8 * 128];
    float spart[32 * 8];
    float c2[32], scl[32], S[32];
};

static __device__ __forceinline__ void mma16816(float* c, const uint32_t* a, const uint32_t* b) {
    asm volatile(
        "mma.sync.aligned.m16n8k16.row.col.f32.bf16.bf16.f32 "
        "{%0,%1,%2,%3},{%4,%5,%6,%7},{%8,%9},{%0,%1,%2,%3};"
        : "+f"(c[0]), "+f"(c[1]), "+f"(c[2]), "+f"(c[3])
        : "r"(a[0]), "r"(a[1]), "r"(a[2]), "r"(a[3]), "r"(b[0]), "r"(b[1]));
}

__global__ void __launch_bounds__(256, 1)
enc_kernel(const float* __restrict__ X, const float* __restrict__ Cg,
           const float* __restrict__ scaleg, float* __restrict__ out)
{
    extern __shared__ char raw[];
    Sm& s = *reinterpret_cast<Sm*>(raw);
    const int tid = threadIdx.x, lane = tid & 31, w = tid >> 5;
    const int g = lane >> 2, t = lane & 3;
    const int b = blockIdx.y, ch = blockIdx.x;
    const float* Xb = X + (size_t)b * 128 * 16384;

    // one-time init: codewords bf16 hi/lo, c2, scale, S
    for (int i = tid; i < 32 * 128; i += 256) {
        int k = i >> 7, d = i & 127;
        float c = Cg[i];
        __nv_bfloat16 h = __float2bfloat16(c);
        s.chi[k * CP + d] = h;
        s.clo[k * CP + d] = __float2bfloat16(c - __bfloat162float(h));
    }
    if (tid < 32) {
        float c2 = 0.f;
        #pragma unroll 8
        for (int d = 0; d < 128; d++) { float c = Cg[tid * 128 + d]; c2 += c * c; }
        s.c2[tid] = c2;
        s.scl[tid] = scaleg[tid];
        s.S[tid] = 0.f;
    }

    // GEMM2 accumulators: warp w owns d rows [16w,16w+16), all K. e[j] = k-tile j (cols 8j..8j+7)
    float e[4][4];
    #pragma unroll
    for (int j = 0; j < 4; j++) { e[j][0] = 0.f; e[j][1] = 0.f; e[j][2] = 0.f; e[j][3] = 0.f; }

    // GEMM1 warp tile: k-rows mk..mk+15, n-col tiles jb..jb+3
    const int mk = (w >> 2) * 16;
    const int jb = (w & 3) * 4;

    for (int st = 0; st < 8; st++) {
        __syncthreads();  // previous iteration's GEMM2 reads done; smem reusable
        const int n0 = ch * 1024 + st * 128;

        // ---- load X tile [d][n] fp32 -> bf16 hi/lo + x2 partials ----
        {
            const int nl = lane * 4;
            float p0 = 0.f, p1 = 0.f, p2 = 0.f, p3 = 0.f;
            #pragma unroll
            for (int i = 0; i < 16; i++) {
                const int d = w * 16 + i;
                float4 v = *reinterpret_cast<const float4*>(Xb + (size_t)d * 16384 + n0 + nl);
                __nv_bfloat16 h0 = __float2bfloat16(v.x), h1 = __float2bfloat16(v.y);
                __nv_bfloat16 h2 = __float2bfloat16(v.z), h3 = __float2bfloat16(v.w);
                __nv_bfloat162 H0; H0.x = h0; H0.y = h1;
                __nv_bfloat162 H1; H1.x = h2; H1.y = h3;
                __nv_bfloat162 L0, L1;
                L0.x = __float2bfloat16(v.x - __bfloat162float(h0));
                L0.y = __float2bfloat16(v.y - __bfloat162float(h1));
                L1.x = __float2bfloat16(v.z - __bfloat162float(h2));
                L1.y = __float2bfloat16(v.w - __bfloat162float(h3));
                *reinterpret_cast<__nv_bfloat162*>(&s.xhi[d * XP + nl])     = H0;
                *reinterpret_cast<__nv_bfloat162*>(&s.xhi[d * XP + nl + 2]) = H1;
                *reinterpret_cast<__nv_bfloat162*>(&s.xlo[d * XP + nl])     = L0;
                *reinterpret_cast<__nv_bfloat162*>(&s.xlo[d * XP + nl + 2]) = L1;
                p0 += v.x * v.x; p1 += v.y * v.y; p2 += v.z * v.z; p3 += v.w * v.w;
            }
            *reinterpret_cast<float4*>(&s.x2p[w * 128 + nl]) = make_float4(p0, p1, p2, p3);
        }
        __syncthreads();

        if (tid < 128) {
            float sum = 0.f;
            #pragma unroll
            for (int q = 0; q < 8; q++) sum += s.x2p[q * 128 + tid];
            s.x2[tid] = sum;
        }

        // ---- GEMM1: xc^T[k][n] = C * X  (A = C[k][d], B = X[d][n]; kdim = d) ----
        float acc1[4][4];
        #pragma unroll
        for (int j = 0; j < 4; j++) { acc1[j][0] = 0.f; acc1[j][1] = 0.f; acc1[j][2] = 0.f; acc1[j][3] = 0.f; }
        for (int kd = 0; kd < 8; kd++) {
            const int d0 = kd * 16;
            uint32_t ah[4], al[4];
            ah[0] = *reinterpret_cast<const uint32_t*>(&s.chi[(mk + g) * CP + d0 + 2 * t]);
            ah[1] = *reinterpret_cast<const uint32_t*>(&s.chi[(mk + g + 8) * CP + d0 + 2 * t]);
            ah[2] = *reinterpret_cast<const uint32_t*>(&s.chi[(mk + g) * CP + d0 + 2 * t + 8]);
            ah[3] = *reinterpret_cast<const uint32_t*>(&s.chi[(mk + g + 8) * CP + d0 + 2 * t + 8]);
            al[0] = *reinterpret_cast<const uint32_t*>(&s.clo[(mk + g) * CP + d0 + 2 * t]);
            al[1] = *reinterpret_cast<const uint32_t*>(&s.clo[(mk + g + 8) * CP + d0 + 2 * t]);
            al[2] = *reinterpret_cast<const uint32_t*>(&s.clo[(mk + g) * CP + d0 + 2 * t + 8]);
            al[3] = *reinterpret_cast<const uint32_t*>(&s.clo[(mk + g + 8) * CP + d0 + 2 * t + 8]);
            #pragma unroll
            for (int j = 0; j < 4; j++) {
                const int nc = (jb + j) * 8;
                uint32_t bh[2], bl[2];
                uint16_t u0, u1;
                u0 = *reinterpret_cast<const uint16_t*>(&s.xhi[(d0 + 2 * t) * XP + nc + g]);
                u1 = *reinterpret_cast<const uint16_t*>(&s.xhi[(d0 + 2 * t + 1) * XP + nc + g]);
                bh[0] = (uint32_t)u0 | ((uint32_t)u1 << 16);
                u0 = *reinterpret_cast<const uint16_t*>(&s.xhi[(d0 + 2 * t + 8) * XP + nc + g]);
                u1 = *reinterpret_cast<const uint16_t*>(&s.xhi[(d0 + 2 * t + 9) * XP + nc + g]);
                bh[1] = (uint32_t)u0 | ((uint32_t)u1 << 16);
                u0 = *reinterpret_cast<const uint16_t*>(&s.xlo[(d0 + 2 * t) * XP + nc + g]);
                u1 = *reinterpret_cast<const uint16_t*>(&s.xlo[(d0 + 2 * t + 1) * XP + nc + g]);
                bl[0] = (uint32_t)u0 | ((uint32_t)u1 << 16);
                u0 = *reinterpret_cast<const uint16_t*>(&s.xlo[(d0 + 2 * t + 8) * XP + nc + g]);
                u1 = *reinterpret_cast<const uint16_t*>(&s.xlo[(d0 + 2 * t + 9) * XP + nc + g]);
                bl[1] = (uint32_t)u0 | ((uint32_t)u1 << 16);
                mma16816(acc1[j], ah, bh);  // C_hi * X_hi
                mma16816(acc1[j], al, bh);  // C_lo * X_hi
                mma16816(acc1[j], ah, bl);  // C_hi * X_lo
            }
        }
        __syncthreads();  // x2 ready for all; per-warp acc1 done

        // ---- sl epilogue: sl = scale_k * (x2 - 2*xc + c2) ----
        #pragma unroll
        for (int j = 0; j < 4; j++) {
            const int nn = (jb + j) * 8 + 2 * t;
            const int k0 = mk + g, k1 = mk + g + 8;
            s.slA[k0 * SP + nn]     = s.scl[k0] * (s.x2[nn]     - 2.f * acc1[j][0] + s.c2[k0]);
            s.slA[k0 * SP + nn + 1] = s.scl[k0] * (s.x2[nn + 1] - 2.f * acc1[j][1] + s.c2[k0]);
            s.slA[k1 * SP + nn]     = s.scl[k1] * (s.x2[nn]     - 2.f * acc1[j][2] + s.c2[k1]);
            s.slA[k1 * SP + nn + 1] = s.scl[k1] * (s.x2[nn + 1] - 2.f * acc1[j][3] + s.c2[k1]);
        }
        __syncthreads();

        // ---- softmax over k for each n (one thread per n) ----
        if (tid < 128) {
            float v[32];
            float m = -1e30f;
            #pragma unroll
            for (int k = 0; k < 32; k++) { v[k] = s.slA[k * SP + tid]; m = fmaxf(m, v[k]); }
            float sum = 0.f;
            #pragma unroll
            for (int k = 0; k < 32; k++) { v[k] = __expf(v[k] - m); sum += v[k]; }
            const float inv = 1.f / sum;
            #pragma unroll
            for (int k = 0; k < 32; k++) {
                float a = v[k] * inv;
                __nv_bfloat16 h = __float2bfloat16(a);
                s.ahi[k * AP + tid] = h;
                s.alo[k * AP + tid] = __float2bfloat16(a - __bfloat162float(h));
                s.slA[k * SP + tid] = a;  // fp32 A for exact S reduction
            }
        }
        __syncthreads();

        // ---- S_k partial sums ----
        {
            const int k = tid >> 3, seg = tid & 7;
            const float* p = &s.slA[k * SP + seg * 16];
            float sum = 0.f;
            #pragma unroll
            for (int i = 0; i < 16; i++) sum += p[i];
            s.spart[k * 8 + seg] = sum;
        }
        __syncthreads();
        if (tid < 32) {
            float ss = 0.f;
            #pragma unroll
            for (int q = 0; q < 8; q++) ss += s.spart[tid * 8 + q];
            s.S[tid] += ss;
        }

        // ---- GEMM2: E^T[d][k] += X^T * A  (A-op = X[d][n], B-op = Amat[k][n]; kdim = n) ----
        for (int kn = 0; kn < 8; kn++) {
            const int nn = kn * 16;
            uint32_t xh[4], xl[4];
            xh[0] = *reinterpret_cast<const uint32_t*>(&s.xhi[(16 * w + g) * XP + nn + 2 * t]);
            xh[1] = *reinterpret_cast<const uint32_t*>(&s.xhi[(16 * w + g + 8) * XP + nn + 2 * t]);
            xh[2] = *reinterpret_cast<const uint32_t*>(&s.xhi[(16 * w + g) * XP + nn + 2 * t + 8]);
            xh[3] = *reinterpret_cast<const uint32_t*>(&s.xhi[(16 * w + g + 8) * XP + nn + 2 * t + 8]);
            xl[0] = *reinterpret_cast<const uint32_t*>(&s.xlo[(16 * w + g) * XP + nn + 2 * t]);
            xl[1] = *reinterpret_cast<const uint32_t*>(&s.xlo[(16 * w + g + 8) * XP + nn + 2 * t]);
            xl[2] = *reinterpret_cast<const uint32_t*>(&s.xlo[(16 * w + g) * XP + nn + 2 * t + 8]);
            xl[3] = *reinterpret_cast<const uint32_t*>(&s.xlo[(16 * w + g + 8) * XP + nn + 2 * t + 8]);
            #pragma unroll
            for (int j = 0; j < 4; j++) {
                const int kc = j * 8;
                uint32_t bh[2], bl[2];
                bh[0] = *reinterpret_cast<const uint32_t*>(&s.ahi[(kc + g) * AP + nn + 2 * t]);
                bh[1] = *reinterpret_cast<const uint32_t*>(&s.ahi[(kc + g) * AP + nn + 2 * t + 8]);
                bl[0] = *reinterpret_cast<const uint32_t*>(&s.alo[(kc + g) * AP + nn + 2 * t]);
                bl[1] = *reinterpret_cast<const uint32_t*>(&s.alo[(kc + g) * AP + nn + 2 * t + 8]);
                mma16816(e[j], xh, bh);  // X_hi * A_hi
                mma16816(e[j], xh, bl);  // X_hi * A_lo
                mma16816(e[j], xl, bh);  // X_lo * A_hi
            }
        }
    }

    __syncthreads();  // final S ready

    // ---- epilogue: atomicAdd partial (sum_n A x - S_k c) into out[b][k][d] ----
    float* outb = out + (size_t)b * 32 * 128;
    #pragma unroll
    for (int j = 0; j < 4; j++) {
        const int k0 = j * 8 + 2 * t, d0 = 16 * w + g;
        atomicAdd(&outb[k0 * 128 + d0],           e[j][0] - s.S[k0]     * Cg[k0 * 128 + d0]);
        atomicAdd(&outb[(k0 + 1) * 128 + d0],     e[j][1] - s.S[k0 + 1] * Cg[(k0 + 1) * 128 + d0]);
        atomicAdd(&outb[k0 * 128 + d0 + 8],       e[j][2] - s.S[k0]     * Cg[k0 * 128 + d0 + 8]);
        atomicAdd(&outb[(k0 + 1) * 128 + d0 + 8], e[j][3] - s.S[k0 + 1] * Cg[(k0 + 1) * 128 + d0 + 8]);
    }
}

extern "C" void kernel_launch(void* const* d_in, const int* in_sizes, int n_in,
                              void* d_out, int out_size) {
    const float* X  = (const float*)d_in[0];
    const float* C  = (const float*)d_in[1];
    const float* sc = (const float*)d_in[2];
    float* out = (float*)d_out;

    cudaFuncSetAttribute(enc_kernel, cudaFuncAttributeMaxDynamicSharedMemorySize,
                         (int)sizeof(Sm));
    cudaMemsetAsync(out, 0, (size_t)out_size * sizeof(float));
    dim3 grid(16, 32);
    enc_kernel<<<grid, 256, sizeof(Sm)>>>(X, C, sc, out);
}

// round 3
// speedup vs baseline: 1.3777x; 1.3777x over previous
#include <cuda_runtime.h>
#include <cuda_bf16.h>
#include <cstdint>

#define XP 136   // bf16 pitch for x tiles [d][n] (272B rows: ldmatrix conflict-free)
#define AP 136   // bf16 pitch for A tiles [k][n]
#define CP 136   // bf16 pitch for codeword tiles [k][d]
#define SP 132   // fp32 pitch for sl tile

struct Sm {
    __nv_bfloat16 xhi[128 * XP];
    __nv_bfloat16 xlo[128 * XP];
    __nv_bfloat16 chi[32 * CP];
    __nv_bfloat16 ahi[32 * AP];
    __nv_bfloat16 alo[32 * AP];
    float slA[32 * SP];          // also aliased as x2p (8*128 floats) during load phase
    float x2[128];
    float spart[32 * 8];
    float c2[32], scl[32], S[32];
};

static __device__ __forceinline__ uint32_t sptr(const void* p) {
    return (uint32_t)__cvta_generic_to_shared(p);
}
static __device__ __forceinline__ void ldsm4(uint32_t* r, uint32_t a) {
    asm volatile("ldmatrix.sync.aligned.m8n8.x4.shared.b16 {%0,%1,%2,%3},[%4];"
                 : "=r"(r[0]), "=r"(r[1]), "=r"(r[2]), "=r"(r[3]) : "r"(a));
}
static __device__ __forceinline__ void ldsm4t(uint32_t* r, uint32_t a) {
    asm volatile("ldmatrix.sync.aligned.m8n8.x4.trans.shared.b16 {%0,%1,%2,%3},[%4];"
                 : "=r"(r[0]), "=r"(r[1]), "=r"(r[2]), "=r"(r[3]) : "r"(a));
}
static __device__ __forceinline__ void mma16816(float* c, const uint32_t* a, const uint32_t* b) {
    asm volatile(
        "mma.sync.aligned.m16n8k16.row.col.f32.bf16.bf16.f32 "
        "{%0,%1,%2,%3},{%4,%5,%6,%7},{%8,%9},{%0,%1,%2,%3};"
        : "+f"(c[0]), "+f"(c[1]), "+f"(c[2]), "+f"(c[3])
        : "r"(a[0]), "r"(a[1]), "r"(a[2]), "r"(a[3]), "r"(b[0]), "r"(b[1]));
}

__global__ void __launch_bounds__(256, 2)
enc_kernel(const float* __restrict__ X, const float* __restrict__ Cg,
           const float* __restrict__ scaleg, float* __restrict__ out)
{
    extern __shared__ char raw[];
    Sm& s = *reinterpret_cast<Sm*>(raw);
    const int tid = threadIdx.x, lane = tid & 31, w = tid >> 5;
    const int g = lane >> 2, t = lane & 3;
    const int lr = lane & 15, lh = lane >> 4;            // ldmatrix x4 addressing (A/trans-B)
    const int brow = (lane >> 4) * 8 + (lane & 7);       // ldmatrix x4 addressing (GEMM2 B)
    const int bcol = ((lane >> 3) & 1) * 8;
    const int b = blockIdx.y, ch = blockIdx.x;
    const float* Xb = X + (size_t)b * 128 * 16384;

    for (int i = tid; i < 32 * 128; i += 256) {
        int k = i >> 7, d = i & 127;
        s.chi[k * CP + d] = __float2bfloat16(Cg[i]);
    }
    if (tid < 32) {
        float c2 = 0.f;
        #pragma unroll 8
        for (int d = 0; d < 128; d++) { float c = Cg[tid * 128 + d]; c2 += c * c; }
        s.c2[tid] = c2;
        s.scl[tid] = scaleg[tid];
        s.S[tid] = 0.f;
    }

    float e[4][4];
    #pragma unroll
    for (int j = 0; j < 4; j++) { e[j][0] = 0.f; e[j][1] = 0.f; e[j][2] = 0.f; e[j][3] = 0.f; }

    const int mk = (w >> 2) * 16;   // GEMM1 k-row base
    const int jb = (w & 3) * 4;     // GEMM1 n-tile base

    for (int st = 0; st < 8; st++) {
        __syncthreads();
        const int n0 = ch * 1024 + st * 128;

        // ---- load X tile, split bf16 hi/lo, x2 partials (x2p aliases slA) ----
        {
            float* x2p = s.slA;
            const int nl = lane * 4;
            float p0 = 0.f, p1 = 0.f, p2 = 0.f, p3 = 0.f;
            #pragma unroll
            for (int i = 0; i < 16; i++) {
                const int d = w * 16 + i;
                float4 v = *reinterpret_cast<const float4*>(Xb + (size_t)d * 16384 + n0 + nl);
                __nv_bfloat16 h0 = __float2bfloat16(v.x), h1 = __float2bfloat16(v.y);
                __nv_bfloat16 h2 = __float2bfloat16(v.z), h3 = __float2bfloat16(v.w);
                uint32_t H0 = ((uint32_t)*(uint16_t*)&h0) | ((uint32_t)*(uint16_t*)&h1 << 16);
                uint32_t H1 = ((uint32_t)*(uint16_t*)&h2) | ((uint32_t)*(uint16_t*)&h3 << 16);
                __nv_bfloat16 l0 = __float2bfloat16(v.x - __bfloat162float(h0));
                __nv_bfloat16 l1 = __float2bfloat16(v.y - __bfloat162float(h1));
                __nv_bfloat16 l2 = __float2bfloat16(v.z - __bfloat162float(h2));
                __nv_bfloat16 l3 = __float2bfloat16(v.w - __bfloat162float(h3));
                uint32_t L0 = ((uint32_t)*(uint16_t*)&l0) | ((uint32_t)*(uint16_t*)&l1 << 16);
                uint32_t L1 = ((uint32_t)*(uint16_t*)&l2) | ((uint32_t)*(uint16_t*)&l3 << 16);
                *reinterpret_cast<uint2*>(&s.xhi[d * XP + nl]) = make_uint2(H0, H1);
                *reinterpret_cast<uint2*>(&s.xlo[d * XP + nl]) = make_uint2(L0, L1);
                p0 += v.x * v.x; p1 += v.y * v.y; p2 += v.z * v.z; p3 += v.w * v.w;
            }
            *reinterpret_cast<float4*>(&x2p[w * 128 + nl]) = make_float4(p0, p1, p2, p3);
        }
        __syncthreads();

        if (tid < 128) {
            const float* x2p = s.slA;
            float sum = 0.f;
            #pragma unroll
            for (int q = 0; q < 8; q++) sum += x2p[q * 128 + tid];
            s.x2[tid] = sum;
        }

        // ---- GEMM1: xc^T[k][n] = C_hi * (X_hi + X_lo) ----
        float acc1[4][4];
        #pragma unroll
        for (int j = 0; j < 4; j++) { acc1[j][0] = 0.f; acc1[j][1] = 0.f; acc1[j][2] = 0.f; acc1[j][3] = 0.f; }
        #pragma unroll
        for (int kd = 0; kd < 8; kd++) {
            const int d0 = kd * 16;
            uint32_t ah[4];
            ldsm4(ah, sptr(&s.chi[(mk + lr) * CP + d0 + lh * 8]));
            #pragma unroll
            for (int jp = 0; jp < 2; jp++) {
                const int nc = (jb + jp * 2) * 8;
                uint32_t bh[4], bl[4];
                ldsm4t(bh, sptr(&s.xhi[(d0 + lr) * XP + nc + lh * 8]));
                ldsm4t(bl, sptr(&s.xlo[(d0 + lr) * XP + nc + lh * 8]));
                mma16816(acc1[jp * 2 + 0], ah, bh + 0);
                mma16816(acc1[jp * 2 + 0], ah, bl + 0);
                mma16816(acc1[jp * 2 + 1], ah, bh + 2);
                mma16816(acc1[jp * 2 + 1], ah, bl + 2);
            }
        }
        __syncthreads();   // x2 ready everywhere; x2p dead -> slA writable

        #pragma unroll
        for (int j = 0; j < 4; j++) {
            const int nn = (jb + j) * 8 + 2 * t;
            const int k0 = mk + g, k1 = mk + g + 8;
            s.slA[k0 * SP + nn]     = s.scl[k0] * (s.x2[nn]     - 2.f * acc1[j][0] + s.c2[k0]);
            s.slA[k0 * SP + nn + 1] = s.scl[k0] * (s.x2[nn + 1] - 2.f * acc1[j][1] + s.c2[k0]);
            s.slA[k1 * SP + nn]     = s.scl[k1] * (s.x2[nn]     - 2.f * acc1[j][2] + s.c2[k1]);
            s.slA[k1 * SP + nn + 1] = s.scl[k1] * (s.x2[nn + 1] - 2.f * acc1[j][3] + s.c2[k1]);
        }
        __syncthreads();

        // ---- softmax over k for each n ----
        if (tid < 128) {
            float v[32];
            float m = -1e30f;
            #pragma unroll
            for (int k = 0; k < 32; k++) { v[k] = s.slA[k * SP + tid]; m = fmaxf(m, v[k]); }
            float sum = 0.f;
            #pragma unroll
            for (int k = 0; k < 32; k++) { v[k] = __expf(v[k] - m); sum += v[k]; }
            const float inv = 1.f / sum;
            #pragma unroll
            for (int k = 0; k < 32; k++) {
                float a = v[k] * inv;
                __nv_bfloat16 h = __float2bfloat16(a);
                s.ahi[k * AP + tid] = h;
                s.alo[k * AP + tid] = __float2bfloat16(a - __bfloat162float(h));
                s.slA[k * SP + tid] = a;
            }
        }
        __syncthreads();

        // ---- S_k partials ----
        {
            const int k = tid >> 3, seg = tid & 7;
            const float* p = &s.slA[k * SP + seg * 16];
            float sum = 0.f;
            #pragma unroll
            for (int i = 0; i < 16; i++) sum += p[i];
            s.spart[k * 8 + seg] = sum;
        }
        __syncthreads();
        if (tid < 32) {
            float ss = 0.f;
            #pragma unroll
            for (int q = 0; q < 8; q++) ss += s.spart[tid * 8 + q];
            s.S[tid] += ss;
        }

        // ---- GEMM2: E^T[d][k] += X_hi*A_hi + X_hi*A_lo + X_lo*A_hi ----
        #pragma unroll
        for (int kn = 0; kn < 8; kn++) {
            const int nn = kn * 16;
            uint32_t xh[4], xl[4];
            ldsm4(xh, sptr(&s.xhi[(16 * w + lr) * XP + nn + lh * 8]));
            ldsm4(xl, sptr(&s.xlo[(16 * w + lr) * XP + nn + lh * 8]));
            uint32_t b0h[4], b0l[4], b1h[4], b1l[4];
            ldsm4(b0h, sptr(&s.ahi[brow * AP + nn + bcol]));          // k-tiles 0,1
            ldsm4(b0l, sptr(&s.alo[brow * AP + nn + bcol]));
            ldsm4(b1h, sptr(&s.ahi[(16 + brow) * AP + nn + bcol]));   // k-tiles 2,3
            ldsm4(b1l, sptr(&s.alo[(16 + brow) * AP + nn + bcol]));
            mma16816(e[0], xh, b0h + 0); mma16816(e[0], xh, b0l + 0); mma16816(e[0], xl, b0h + 0);
            mma16816(e[1], xh, b0h + 2); mma16816(e[1], xh, b0l + 2); mma16816(e[1], xl, b0h + 2);
            mma16816(e[2], xh, b1h + 0); mma16816(e[2], xh, b1l + 0); mma16816(e[2], xl, b1h + 0);
            mma16816(e[3], xh, b1h + 2); mma16816(e[3], xh, b1l + 2); mma16816(e[3], xl, b1h + 2);
        }
    }

    __syncthreads();

    float* outb = out + (size_t)b * 32 * 128;
    #pragma unroll
    for (int j = 0; j < 4; j++) {
        const int k0 = j * 8 + 2 * t, d0 = 16 * w + g;
        atomicAdd(&outb[k0 * 128 + d0],           e[j][0] - s.S[k0]     * Cg[k0 * 128 + d0]);
        atomicAdd(&outb[(k0 + 1) * 128 + d0],     e[j][1] - s.S[k0 + 1] * Cg[(k0 + 1) * 128 + d0]);
        atomicAdd(&outb[k0 * 128 + d0 + 8],       e[j][2] - s.S[k0]     * Cg[k0 * 128 + d0 + 8]);
        atomicAdd(&outb[(k0 + 1) * 128 + d0 + 8], e[j][3] - s.S[k0 + 1] * Cg[(k0 + 1) * 128 + d0 + 8]);
    }
}

extern "C" void kernel_launch(void* const* d_in, const int* in_sizes, int n_in,
                              void* d_out, int out_size) {
    const float* X  = (const float*)d_in[0];
    const float* C  = (const float*)d_in[1];
    const float* sc = (const float*)d_in[2];
    float* out = (float*)d_out;

    cudaFuncSetAttribute(enc_kernel, cudaFuncAttributeMaxDynamicSharedMemorySize,
                         (int)sizeof(Sm));
    cudaMemsetAsync(out, 0, (size_t)out_size * sizeof(float));
    dim3 grid(16, 32);
    enc_kernel<<<grid, 256, sizeof(Sm)>>>(X, C, sc, out);
}